// round 3
// baseline (speedup 1.0000x reference)
#include <cuda_runtime.h>
#include <cuda_fp16.h>

// Problem constants
#define NU   100000
#define NI   50000
#define NN   150000            // NU + NI
#define DD   64
#define NNZV 3200000           // symmetrized nnz
#define BB   4096
#define SCAN_BS 1024
#define NB1  ((NN + SCAN_BS - 1) / SCAN_BS)   // 147

// Scratch (device globals: allocation-free per harness rules)
__device__ __half g_xh[NN * DD];     // 19.2 MB  fp16 ping
__device__ __half g_yh[NN * DD];     // 19.2 MB  fp16 pong
__device__ float  g_acc[NN * DD];    // 38.4 MB  fp32 running sum
__device__ int    g_cnt[NN];         // histogram, then scatter cursors
__device__ int    g_rowptr[NN + 1];
__device__ int2   g_edge[NNZV];      // packed {col, val_bits} 25.6 MB
__device__ int    g_bsum[NB1];

// ---------------------------------------------------------------------------
// Prep: convert inputs fp32 -> fp16 into g_xh; zero histogram
// ---------------------------------------------------------------------------
__global__ void k_prep(const float2* __restrict__ ue2, const float2* __restrict__ ie2) {
    int stride = gridDim.x * blockDim.x;
    int tid = blockIdx.x * blockDim.x + threadIdx.x;
    half2* xh2 = (half2*)g_xh;
    const int HALF = NU * 32;              // float2 count for user part
    for (int i = tid; i < NN * 32; i += stride) {
        float2 v = (i < HALF) ? ue2[i] : ie2[i - HALF];
        xh2[i] = __floats2half2_rn(v.x, v.y);
    }
    for (int i = tid; i < NN; i += stride) g_cnt[i] = 0;
}

// ---------------------------------------------------------------------------
// CSR build: histogram -> exclusive scan -> scatter (packed edges)
// ---------------------------------------------------------------------------
__global__ void k_hist(const int* __restrict__ rows) {
    int stride = gridDim.x * blockDim.x;
    for (int e = blockIdx.x * blockDim.x + threadIdx.x; e < NNZV; e += stride)
        atomicAdd(&g_cnt[rows[e]], 1);
}

__global__ void k_scan1() {   // per-block exclusive scan + block totals
    __shared__ int sh[SCAN_BS];
    int t = threadIdx.x;
    int i = blockIdx.x * SCAN_BS + t;
    int v = (i < NN) ? g_cnt[i] : 0;
    sh[t] = v;
    __syncthreads();
    for (int off = 1; off < SCAN_BS; off <<= 1) {
        int y = (t >= off) ? sh[t - off] : 0;
        __syncthreads();
        sh[t] += y;
        __syncthreads();
    }
    if (i < NN) g_rowptr[i] = sh[t] - v;          // exclusive, pre-offset
    if (t == SCAN_BS - 1) g_bsum[blockIdx.x] = sh[t];
}

__global__ void k_scan2() {   // parallel exclusive scan of 147 block sums
    __shared__ int sh[256];
    int t = threadIdx.x;
    int v = (t < NB1) ? g_bsum[t] : 0;
    sh[t] = v;
    __syncthreads();
    for (int off = 1; off < 256; off <<= 1) {
        int y = (t >= off) ? sh[t - off] : 0;
        __syncthreads();
        sh[t] += y;
        __syncthreads();
    }
    if (t < NB1) g_bsum[t] = sh[t] - v;           // exclusive
}

__global__ void k_scan3() {   // add block offsets; init scatter cursors
    int stride = gridDim.x * blockDim.x;
    for (int i = blockIdx.x * blockDim.x + threadIdx.x; i < NN; i += stride) {
        int val = g_rowptr[i] + g_bsum[i >> 10];
        g_rowptr[i] = val;
        g_cnt[i]    = val;    // running write cursor for scatter
    }
    if (blockIdx.x == 0 && threadIdx.x == 0) g_rowptr[NN] = NNZV;
}

__global__ void k_scatter(const int* __restrict__ rows, const int* __restrict__ cols,
                          const float* __restrict__ vals) {
    int stride = gridDim.x * blockDim.x;
    for (int e = blockIdx.x * blockDim.x + threadIdx.x; e < NNZV; e += stride) {
        int r = rows[e];
        int p = atomicAdd(&g_cnt[r], 1);
        g_edge[p] = make_int2(cols[e], __float_as_int(vals[e]));   // one 8B store
    }
}

// ---------------------------------------------------------------------------
// SpMM: one warp per row. Lanes hold D=64 as 2 fp32 accumulators.
// Warp-uniform edge loads (L1 broadcast), fp16 gathers (128B/edge).
// flip=0: read g_xh, write g_yh. flip=1: read g_yh, write g_xh.
// MODE 0: acc = fp32_input_row + y   (layer 1)
// MODE 1: acc += y                   (layers 2,3)
// ---------------------------------------------------------------------------
template <int MODE>
__global__ void k_spmm(int flip,
                       const float2* __restrict__ ue2, const float2* __restrict__ ie2) {
    // Device-side symbol references: valid addresses.
    const half2* __restrict__ xh = (const half2*)(flip ? g_yh : g_xh);
    half2*       __restrict__ yh = (half2*)      (flip ? g_xh : g_yh);

    int r = (blockIdx.x * blockDim.x + threadIdx.x) >> 5;
    if (r >= NN) return;
    int lane = threadIdx.x & 31;

    int s = g_rowptr[r];
    int e = g_rowptr[r + 1];

    float ax = 0.f, ay = 0.f;
#pragma unroll 4
    for (int p = s; p < e; ++p) {
        int2 eg = __ldg(&g_edge[p]);                 // warp-uniform, L1 broadcast
        float v = __int_as_float(eg.y);
        float2 xv = __half22float2(xh[eg.x * 32 + lane]);  // 128B coalesced gather
        ax = fmaf(v, xv.x, ax);
        ay = fmaf(v, xv.y, ay);
    }

    int o = r * 32 + lane;
    yh[o] = __floats2half2_rn(ax, ay);

    float2* a2 = (float2*)g_acc;
    if (MODE == 0) {
        float2 own = (r < NU) ? ue2[o] : ie2[o - NU * 32];
        a2[o] = make_float2(own.x + ax, own.y + ay);
    } else {
        float2 av = a2[o];
        a2[o] = make_float2(av.x + ax, av.y + ay);
    }
}

// ---------------------------------------------------------------------------
// Scorer: warp per (user, item) pair, dot over D=64, scale by 1/16
// ---------------------------------------------------------------------------
__global__ void k_score(const int* __restrict__ uids, const int* __restrict__ iids,
                        float* __restrict__ out) {
    int w = (blockIdx.x * blockDim.x + threadIdx.x) >> 5;
    if (w >= BB) return;
    int lane = threadIdx.x & 31;
    int u  = uids[w];
    int it = iids[w];
    const float2* a2 = (const float2*)g_acc;
    float2 ua = a2[u * 32 + lane];
    float2 ia = a2[(NU + it) * 32 + lane];
    float sres = ua.x * ia.x + ua.y * ia.y;
#pragma unroll
    for (int o = 16; o; o >>= 1) sres += __shfl_xor_sync(0xffffffffu, sres, o);
    if (lane == 0) out[w] = sres * 0.0625f;   // 1/(L+1)^2
}

// ---------------------------------------------------------------------------
extern "C" void kernel_launch(void* const* d_in, const int* in_sizes, int n_in,
                              void* d_out, int out_size) {
    const float* ue   = (const float*)d_in[0];   // user_emb [100000,64]
    const float* ie   = (const float*)d_in[1];   // item_emb [50000,64]
    const float* vals = (const float*)d_in[2];   // adj_vals [3.2M]
    const int*   rows = (const int*)  d_in[3];   // adj_rows [3.2M]
    const int*   cols = (const int*)  d_in[4];   // adj_cols [3.2M]
    const int*   uids = (const int*)  d_in[5];   // user_ids [4096]
    const int*   iids = (const int*)  d_in[6];   // item_ids [4096]
    float*       out  = (float*)d_out;           // scores [4096]

    const float2* ue2 = (const float2*)ue;
    const float2* ie2 = (const float2*)ie;

    k_prep   <<< 2048, 256 >>>(ue2, ie2);
    k_hist   <<< 2048, 256 >>>(rows);
    k_scan1  <<< NB1, SCAN_BS >>>();
    k_scan2  <<< 1, 256 >>>();
    k_scan3  <<< 592, 256 >>>();
    k_scatter<<< 2048, 256 >>>(rows, cols, vals);

    const int spmm_blocks = (NN * 32 + 255) / 256;   // warp per row
    k_spmm<0><<< spmm_blocks, 256 >>>(0, ue2, ie2);  // xh -> yh, acc = x0 + y1
    k_spmm<1><<< spmm_blocks, 256 >>>(1, ue2, ie2);  // yh -> xh, acc += y2
    k_spmm<1><<< spmm_blocks, 256 >>>(0, ue2, ie2);  // xh -> yh, acc += y3

    k_score<<< (BB * 32 + 255) / 256, 256 >>>(uids, iids, out);
}

// round 4
// speedup vs baseline: 1.4285x; 1.4285x over previous
#include <cuda_runtime.h>
#include <cuda_fp16.h>

// Problem constants
#define NU   100000
#define NI   50000
#define NN   150000            // NU + NI
#define DD   64
#define NNZV 3200000           // symmetrized nnz
#define BB   4096
#define SCAN_BS 1024
#define NB1  ((NN + SCAN_BS - 1) / SCAN_BS)   // 147 tiles

// Scratch (device globals; zero-initialized at module load)
__device__ __half g_xh[NN * DD];               // 19.2 MB fp16 ping
__device__ __half g_yh[NN * DD];               // 19.2 MB fp16 pong
__device__ float  g_acc[NN * DD];              // 38.4 MB fp32 running sum
__device__ int    g_cnt[NN];                   // histogram -> scatter cursors (zeroed by k_score)
__device__ int    g_rowptr[NN + 1];
__device__ int2   g_edge[NNZV];                // packed {col, val_bits}
__device__ unsigned long long g_tile_desc[NB1];// lookback: {status<<32 | value} (zeroed by k_score)

// ---------------------------------------------------------------------------
// Launch 0: fused prep (fp32 -> fp16 convert) + degree histogram.
// g_cnt and g_tile_desc are pre-zeroed (static init on first call, k_score on
// every subsequent replay).
// ---------------------------------------------------------------------------
__global__ void k_hist_prep(const float2* __restrict__ ue2, const float2* __restrict__ ie2,
                            const int* __restrict__ rows) {
    int stride = gridDim.x * blockDim.x;
    int tid = blockIdx.x * blockDim.x + threadIdx.x;
    half2* xh2 = (half2*)g_xh;
    const int HALF = NU * 32;
    for (int i = tid; i < NN * 32; i += stride) {
        float2 v = (i < HALF) ? ue2[i] : ie2[i - HALF];
        xh2[i] = __floats2half2_rn(v.x, v.y);
    }
    for (int e = tid; e < NNZV; e += stride)
        atomicAdd(&g_cnt[rows[e]], 1);
}

// ---------------------------------------------------------------------------
// Launch 1: single-kernel exclusive scan (decoupled lookback).
// 147 blocks of 1024 — all resident simultaneously on 148 SMs, no deadlock.
// Descriptor: 64-bit {status: 0=invalid 1=aggregate 2=prefix | value}.
// Writes g_rowptr (exclusive) and g_cnt (scatter cursors).
// ---------------------------------------------------------------------------
__global__ void k_scan() {
    __shared__ int sh[SCAN_BS];
    __shared__ int sh_excl;
    int t = threadIdx.x;
    int b = blockIdx.x;
    int i = b * SCAN_BS + t;
    int v = (i < NN) ? g_cnt[i] : 0;
    sh[t] = v;
    __syncthreads();
#pragma unroll
    for (int off = 1; off < SCAN_BS; off <<= 1) {
        int y = (t >= off) ? sh[t - off] : 0;
        __syncthreads();
        sh[t] += y;
        __syncthreads();
    }
    int incl = sh[t];
    int total = sh[SCAN_BS - 1];

    if (b == 0) {
        if (t == 0) {
            unsigned long long d = (2ull << 32) | (unsigned)total;   // prefix
            *(volatile unsigned long long*)&g_tile_desc[0] = d;
            sh_excl = 0;
        }
    } else {
        if (t == 0) {   // publish aggregate immediately
            unsigned long long d = (1ull << 32) | (unsigned)total;
            *(volatile unsigned long long*)&g_tile_desc[b] = d;
        }
        if (t < 32) {   // warp-parallel lookback
            int excl = 0;
            int j = b - 1 - t;          // lane 0 = nearest predecessor
            while (true) {
                int st, val;
                do {
                    if (j >= 0) {
                        unsigned long long d = *(volatile unsigned long long*)&g_tile_desc[j];
                        st  = (int)(d >> 32);
                        val = (int)(d & 0xffffffffu);
                    } else { st = 2; val = 0; }
                } while (__any_sync(0xffffffffu, st == 0));
                unsigned pm = __ballot_sync(0xffffffffu, st == 2);
                if (pm) {
                    int p = __ffs(pm) - 1;                  // nearest prefix lane
                    int contrib = (t <= p) ? val : 0;
                    excl += __reduce_add_sync(0xffffffffu, contrib);
                    break;
                }
                excl += __reduce_add_sync(0xffffffffu, val);
                j -= 32;
            }
            if (t == 0) {
                sh_excl = excl;
                unsigned long long d = (2ull << 32) | (unsigned)(excl + total);
                *(volatile unsigned long long*)&g_tile_desc[b] = d;
            }
        }
    }
    __syncthreads();
    int base = sh_excl;
    if (i < NN) {
        int ex = base + incl - v;      // exclusive
        g_rowptr[i] = ex;
        g_cnt[i]    = ex;              // scatter cursor
    }
    if (b == NB1 - 1 && t == 0) g_rowptr[NN] = NNZV;
}

// ---------------------------------------------------------------------------
// Launch 2: scatter edges into CSR order (one 8B store per edge)
// ---------------------------------------------------------------------------
__global__ void k_scatter(const int* __restrict__ rows, const int* __restrict__ cols,
                          const float* __restrict__ vals) {
    int stride = gridDim.x * blockDim.x;
    for (int e = blockIdx.x * blockDim.x + threadIdx.x; e < NNZV; e += stride) {
        int r = rows[e];
        int p = atomicAdd(&g_cnt[r], 1);
        g_edge[p] = make_int2(cols[e], __float_as_int(vals[e]));
    }
}

// ---------------------------------------------------------------------------
// Launches 3-5: SpMM. One warp per row; lanes hold D=64 as 2 fp32 accums.
// Edges batch-loaded 32-wide coalesced, staged in smem, broadcast via LDS.
// unroll 8 -> 8 independent 128B gathers in flight per warp.
// flip=0: g_xh -> g_yh ; flip=1: g_yh -> g_xh
// MODE 0: acc = fp32_input + y (layer 1);  MODE 1: acc += y
// ---------------------------------------------------------------------------
template <int MODE>
__global__ void k_spmm(int flip,
                       const float2* __restrict__ ue2, const float2* __restrict__ ie2) {
    const half2* __restrict__ xh = (const half2*)(flip ? g_yh : g_xh);
    half2*       __restrict__ yh = (half2*)      (flip ? g_xh : g_yh);

    __shared__ int2 sm[8][32];
    int w = threadIdx.x >> 5;
    int lane = threadIdx.x & 31;
    int r = (blockIdx.x * blockDim.x + threadIdx.x) >> 5;
    if (r >= NN) return;

    int s = g_rowptr[r];
    int e = g_rowptr[r + 1];

    float ax = 0.f, ay = 0.f;
    for (int p = s; p < e; p += 32) {
        int pi = p + lane;
        if (pi < e) sm[w][lane] = __ldg(&g_edge[pi]);
        __syncwarp();
        int n = min(32, e - p);
#pragma unroll 8
        for (int j = 0; j < n; ++j) {
            int2 eg = sm[w][j];                               // LDS broadcast
            float v = __int_as_float(eg.y);
            float2 xv = __half22float2(xh[eg.x * 32 + lane]); // 128B coalesced gather
            ax = fmaf(v, xv.x, ax);
            ay = fmaf(v, xv.y, ay);
        }
        __syncwarp();
    }

    int o = r * 32 + lane;
    yh[o] = __floats2half2_rn(ax, ay);

    float2* a2 = (float2*)g_acc;
    if (MODE == 0) {
        float2 own = (r < NU) ? ue2[o] : ie2[o - NU * 32];
        a2[o] = make_float2(own.x + ax, own.y + ay);
    } else {
        float2 av = a2[o];
        a2[o] = make_float2(av.x + ax, av.y + ay);
    }
}

// ---------------------------------------------------------------------------
// Launch 6: scorer + reset g_cnt / g_tile_desc for the next replay
// ---------------------------------------------------------------------------
__global__ void k_score(const int* __restrict__ uids, const int* __restrict__ iids,
                        float* __restrict__ out) {
    int gtid = blockIdx.x * blockDim.x + threadIdx.x;
    int w = gtid >> 5;
    int lane = threadIdx.x & 31;
    if (w < BB) {
        int u  = uids[w];
        int it = iids[w];
        const float2* a2 = (const float2*)g_acc;
        float2 ua = a2[u * 32 + lane];
        float2 ia = a2[(NU + it) * 32 + lane];
        float sres = ua.x * ia.x + ua.y * ia.y;
#pragma unroll
        for (int o = 16; o; o >>= 1) sres += __shfl_xor_sync(0xffffffffu, sres, o);
        if (lane == 0) out[w] = sres * 0.0625f;   // 1/(L+1)^2
    }
    // reset state for next replay (deterministic: runs identically every call)
    int stride = gridDim.x * blockDim.x;
    for (int i = gtid; i < NN; i += stride) g_cnt[i] = 0;
    for (int i = gtid; i < NB1; i += stride) g_tile_desc[i] = 0ull;
}

// ---------------------------------------------------------------------------
extern "C" void kernel_launch(void* const* d_in, const int* in_sizes, int n_in,
                              void* d_out, int out_size) {
    const float* ue   = (const float*)d_in[0];
    const float* ie   = (const float*)d_in[1];
    const float* vals = (const float*)d_in[2];
    const int*   rows = (const int*)  d_in[3];
    const int*   cols = (const int*)  d_in[4];
    const int*   uids = (const int*)  d_in[5];
    const int*   iids = (const int*)  d_in[6];
    float*       out  = (float*)d_out;

    const float2* ue2 = (const float2*)ue;
    const float2* ie2 = (const float2*)ie;

    k_hist_prep<<< 2048, 256 >>>(ue2, ie2, rows);     // launch 0
    k_scan     <<< NB1, SCAN_BS >>>();                // launch 1
    k_scatter  <<< 2048, 256 >>>(rows, cols, vals);   // launch 2

    const int spmm_blocks = (NN * 32 + 255) / 256;
    k_spmm<0><<< spmm_blocks, 256 >>>(0, ue2, ie2);   // launch 3  <- ncu capture
    k_spmm<1><<< spmm_blocks, 256 >>>(1, ue2, ie2);   // launch 4
    k_spmm<1><<< spmm_blocks, 256 >>>(0, ue2, ie2);   // launch 5

    k_score<<< 512, 256 >>>(uids, iids, out);         // launch 6 (+state reset)
}